// round 11
// baseline (speedup 1.0000x reference)
#include <cuda_runtime.h>
#include <cuda_bf16.h>
#include <cstdint>

// Problem geometry (fixed by setup_inputs)
#define BG    256
#define NA    512
#define NLIG  128
#define TOPK  64
#define NSEL  128
#define DIM   1024
#define NEBS  8       // e-tiles of 128

// ---------------- scratch (__device__ globals; no allocation allowed) -------
__device__ int   g_idx[BG * NSEL];
__device__ float g_spart[BG * NSEL * NEBS];
__device__ __nv_bfloat16 g_Ahi[(size_t)BG * NSEL * DIM];
__device__ __nv_bfloat16 g_Alo[(size_t)BG * NSEL * DIM];
__device__ __nv_bfloat16 g_Whi[(size_t)DIM * DIM];
__device__ __nv_bfloat16 g_Wlo[(size_t)DIM * DIM];

// ---------------- helpers ---------------------------------------------------
__device__ __forceinline__ uint32_t smem_u32(const void* p) {
    uint32_t a;
    asm("{ .reg .u64 t; cvta.to.shared.u64 t, %1; cvt.u32.u64 %0, t; }" : "=r"(a) : "l"(p));
    return a;
}
__device__ __forceinline__ void cp16(uint32_t dst, const void* src) {
    asm volatile("cp.async.cg.shared.global [%0], [%1], 16;" :: "r"(dst), "l"(src));
}
__device__ __forceinline__ void cp_commit() { asm volatile("cp.async.commit_group;" ::: "memory"); }
template <int N> __device__ __forceinline__ void cp_wait() {
    asm volatile("cp.async.wait_group %0;" :: "n"(N) : "memory");
}
__device__ __forceinline__ void ldsm_x4(uint32_t* r, uint32_t addr) {
    asm volatile("ldmatrix.sync.aligned.m8n8.x4.shared.b16 {%0,%1,%2,%3}, [%4];"
                 : "=r"(r[0]), "=r"(r[1]), "=r"(r[2]), "=r"(r[3]) : "r"(addr));
}
__device__ __forceinline__ void mma_bf16(float* d, const uint32_t* a, uint32_t b0, uint32_t b1) {
    asm volatile("mma.sync.aligned.m16n8k16.row.col.f32.bf16.bf16.f32 "
                 "{%0,%1,%2,%3}, {%4,%5,%6,%7}, {%8,%9}, {%0,%1,%2,%3};"
                 : "+f"(d[0]), "+f"(d[1]), "+f"(d[2]), "+f"(d[3])
                 : "r"(a[0]), "r"(a[1]), "r"(a[2]), "r"(a[3]), "r"(b0), "r"(b1));
}
// tanh via exact identity 1 - 2/(e^{2x}+1) with MUFU ex2/rcp (~1e-6 error)
__device__ __forceinline__ float tanh_fast(float x) {
    float e, r;
    asm("ex2.approx.f32 %0, %1;" : "=f"(e) : "f"(x * 2.885390081777927f));
    asm("rcp.approx.f32 %0, %1;" : "=f"(r) : "f"(e + 1.0f));
    return fmaf(-2.0f, r, 1.0f);
}

// ---------------------------------------------------------------------------
// Kernel 1: FUSED selection + gather/split of A.
// One block of 512 threads per graph. Phase 1: centroids + distances +
// deterministic rank top-K into smem (and g_idx for pool). Phase 2: all 512
// threads gather the 128 selected h rows and write (A_hi, A_lo) bf16.
// ---------------------------------------------------------------------------
__global__ __launch_bounds__(512)
void select_split_kernel(const float* __restrict__ coords, const float* __restrict__ h) {
    const int b = blockIdx.x;
    const int t = threadIdx.x;  // 0..511

    __shared__ float px[16], py[16], pz[16];
    __shared__ float cent[6];
    __shared__ float d2[NA];
    __shared__ int   sIdx[NSEL];

    const float* cp = coords + (size_t)(b * NA + t) * 3;
    float x = cp[0], y = cp[1], z = cp[2];

    float wx = x, wy = y, wz = z;
#pragma unroll
    for (int o = 16; o > 0; o >>= 1) {
        wx += __shfl_down_sync(0xffffffffu, wx, o);
        wy += __shfl_down_sync(0xffffffffu, wy, o);
        wz += __shfl_down_sync(0xffffffffu, wz, o);
    }
    const int wid = t >> 5, lane = t & 31;
    if (lane == 0) { px[wid] = wx; py[wid] = wy; pz[wid] = wz; }
    __syncthreads();

    if (t == 0) {
        float tx = 0, ty = 0, tz = 0, lx = 0, ly = 0, lz = 0;
        for (int i = 0; i < 16; i++) { tx += px[i]; ty += py[i]; tz += pz[i]; }
        for (int i = 0; i < 4; i++)  { lx += px[i]; ly += py[i]; lz += pz[i]; }
        const float invl = 1.0f / NLIG, invp = 1.0f / (NA - NLIG);
        cent[3] = lx * invl;        cent[4] = ly * invl;        cent[5] = lz * invl;
        cent[0] = (tx - lx) * invp; cent[1] = (ty - ly) * invp; cent[2] = (tz - lz) * invp;
    }
    __syncthreads();

    float cx, cy, cz;
    if (t < NLIG) { cx = cent[0]; cy = cent[1]; cz = cent[2]; }
    else          { cx = cent[3]; cy = cent[4]; cz = cent[5]; }
    const float dx = x - cx, dy = y - cy, dz = z - cz;
    d2[t] = dx * dx + dy * dy + dz * dz;
    __syncthreads();

    const float mine = d2[t];
    int rank = 0;
    if (t < NLIG) {
        for (int j = 0; j < NLIG; j++) {
            const float o = d2[j];
            rank += (o < mine) || (o == mine && j < t);
        }
        if (rank < TOPK) { sIdx[TOPK + rank] = t; g_idx[b * NSEL + TOPK + rank] = t; }
    } else {
        for (int j = NLIG; j < NA; j++) {
            const float o = d2[j];
            rank += (o < mine) || (o == mine && j < t);
        }
        if (rank < TOPK) { sIdx[rank] = t; g_idx[b * NSEL + rank] = t; }
    }
    __syncthreads();

    // Phase 2: gather + split. 128 rows x 256 float4 = 32768 float4, 512 threads.
#pragma unroll
    for (int j = 0; j < 64; j++) {
        const int i = t + j * 512;
        const int r = i >> 8, c4 = i & 255;
        const float4 v = *reinterpret_cast<const float4*>(
            h + ((size_t)(b * NA + sIdx[r])) * DIM + c4 * 4);
        __nv_bfloat162 h01 = __floats2bfloat162_rn(v.x, v.y);
        __nv_bfloat162 h23 = __floats2bfloat162_rn(v.z, v.w);
        __nv_bfloat162 l01 = __floats2bfloat162_rn(v.x - __bfloat162float(h01.x),
                                                   v.y - __bfloat162float(h01.y));
        __nv_bfloat162 l23 = __floats2bfloat162_rn(v.z - __bfloat162float(h23.x),
                                                   v.w - __bfloat162float(h23.y));
        const size_t o = ((size_t)(b * NSEL + r)) * DIM + c4 * 4;
        *reinterpret_cast<__nv_bfloat162*>(g_Ahi + o)     = h01;
        *reinterpret_cast<__nv_bfloat162*>(g_Ahi + o + 2) = h23;
        *reinterpret_cast<__nv_bfloat162*>(g_Alo + o)     = l01;
        *reinterpret_cast<__nv_bfloat162*>(g_Alo + o + 2) = l23;
    }
}

// ---------------------------------------------------------------------------
// Kernel 2: split W -> (W_hi, W_lo) bf16
// ---------------------------------------------------------------------------
__global__ void split_w_kernel(const float* __restrict__ W) {
    const size_t i = (size_t)blockIdx.x * 256 + threadIdx.x;
    const float4 v = reinterpret_cast<const float4*>(W)[i];
    __nv_bfloat162 h01 = __floats2bfloat162_rn(v.x, v.y);
    __nv_bfloat162 h23 = __floats2bfloat162_rn(v.z, v.w);
    __nv_bfloat162 l01 = __floats2bfloat162_rn(v.x - __bfloat162float(h01.x),
                                               v.y - __bfloat162float(h01.y));
    __nv_bfloat162 l23 = __floats2bfloat162_rn(v.z - __bfloat162float(h23.x),
                                               v.w - __bfloat162float(h23.y));
    const size_t o = i * 4;
    *reinterpret_cast<__nv_bfloat162*>(g_Whi + o)     = h01;
    *reinterpret_cast<__nv_bfloat162*>(g_Whi + o + 2) = h23;
    *reinterpret_cast<__nv_bfloat162*>(g_Wlo + o)     = l01;
    *reinterpret_cast<__nv_bfloat162*>(g_Wlo + o + 2) = l23;
}

// ---------------------------------------------------------------------------
// Kernel 3: HMMA bf16 split-GEMM + fused tanh/v epilogue.
// Grid (8, 128): x = 128-wide e-tile, y = pair of graphs (2 per CTA).
// 8 warps (4 M x 2 N), warp tile 32x64, 3 HMMA passes (hh, hl, lh).
// Kc=64, 3-stage ring, ONE sync per stage; loads for stage s+2 issued
// eagerly RIGHT AFTER the top-of-stage sync (buffer freed at s-1, the sync
// proves every warp left it) so the LSU burst overlaps this stage's MMAs
// and is off the barrier-critical tail.
// 32 stages = 2 graphs x 16 k-chunks; graph-0 epilogue runs inline.
// smem: red 2KB | 3 stages x 64KB = 198656 B.
// ---------------------------------------------------------------------------
#define NSTG_TOT  32
#define STG_BYTES 65536
#define A_HI_OFF  0
#define A_LO_OFF  16384
#define B_HI_OFF  32768
#define B_LO_OFF  49152
#define RED_BYTES 2048
#define GEMM_SMEM (RED_BYTES + 3 * STG_BYTES)

__global__ __launch_bounds__(256, 1)
void gemm_hmma_kernel(const float* __restrict__ bias, const float* __restrict__ vvec) {
    extern __shared__ __align__(1024) char smem[];
    const uint32_t sb = smem_u32(smem);
    const int tid = threadIdx.x, wid = tid >> 5, lane = tid & 31;
    const int eb = blockIdx.x, b0 = blockIdx.y * 2;
    const int wm = wid >> 1, wn = wid & 1;     // 4 M x 2 N, warp tile 32x64

    const char* Ah[2] = { (const char*)g_Ahi + (size_t)b0 * NSEL * 2048,
                          (const char*)g_Ahi + (size_t)(b0 + 1) * NSEL * 2048 };
    const char* Al[2] = { (const char*)g_Alo + (size_t)b0 * NSEL * 2048,
                          (const char*)g_Alo + (size_t)(b0 + 1) * NSEL * 2048 };
    const char* Bh = (const char*)g_Whi + (size_t)eb * 128 * 2048;
    const char* Bl = (const char*)g_Wlo + (size_t)eb * 128 * 2048;

    float* red = reinterpret_cast<float*>(smem);   // [2][128][2]

    // stage loader: 4 tiles of 128 rows x 128 bytes, XOR-swizzled
    auto load_stage = [&](int S, int buf) {
        const int g = S >> 4, kc = S & 15;
        const uint32_t base = sb + RED_BYTES + buf * STG_BYTES;
        const int k0b = kc * 128;
#pragma unroll
        for (int j = 0; j < 4; j++) {
            const int i = tid + j * 256;
            const int r = i >> 3, sg = i & 7;
            const uint32_t off = r * 128 + ((sg * 16) ^ ((r & 7) << 4));
            const size_t go = (size_t)r * 2048 + k0b + sg * 16;
            cp16(base + A_HI_OFF + off, Ah[g] + go);
            cp16(base + A_LO_OFF + off, Al[g] + go);
            cp16(base + B_HI_OFF + off, Bh + go);
            cp16(base + B_LO_OFF + off, Bl + go);
        }
        cp_commit();
    };

    float acc[2][8][4];
#pragma unroll
    for (int mi = 0; mi < 2; mi++)
#pragma unroll
        for (int nf = 0; nf < 8; nf++)
#pragma unroll
            for (int c = 0; c < 4; c++) acc[mi][nf][c] = 0.0f;

    // per-lane ldmatrix address components
    const int arow = lane & 15;
    const uint32_t a_kh = (lane >> 4) * 16;
    const uint32_t a_xor = (uint32_t)((arow & 7) << 4);
    uint32_t a_base[2];
#pragma unroll
    for (int mi = 0; mi < 2; mi++)
        a_base[mi] = (uint32_t)((wm * 32 + mi * 16 + arow) * 128);

    const int brl = (lane & 7) + ((lane >> 4) << 3);
    const uint32_t b_kh = ((lane >> 3) & 1) * 16;
    const uint32_t b_xor = (uint32_t)((lane & 7) << 4);
    uint32_t b_base[4];
#pragma unroll
    for (int nq = 0; nq < 4; nq++)
        b_base[nq] = (uint32_t)((wn * 64 + nq * 16 + brl) * 128);

    // epilogue: tanh + v-dot on this thread's accs, write per-graph red slab
    auto epilogue = [&](int g) {
        float p[4] = {0.f, 0.f, 0.f, 0.f};
#pragma unroll
        for (int mi = 0; mi < 2; mi++)
#pragma unroll
            for (int nf = 0; nf < 8; nf++) {
                const int e0 = eb * 128 + wn * 64 + nf * 8 + (lane & 3) * 2;
                const float bb0 = __ldg(bias + e0), bb1 = __ldg(bias + e0 + 1);
                const float vv0 = __ldg(vvec + e0), vv1 = __ldg(vvec + e0 + 1);
                p[mi * 2 + 0] += tanh_fast(acc[mi][nf][0] + bb0) * vv0
                               + tanh_fast(acc[mi][nf][1] + bb1) * vv1;
                p[mi * 2 + 1] += tanh_fast(acc[mi][nf][2] + bb0) * vv0
                               + tanh_fast(acc[mi][nf][3] + bb1) * vv1;
            }
#pragma unroll
        for (int i = 0; i < 4; i++) {
            p[i] += __shfl_xor_sync(0xffffffffu, p[i], 1);
            p[i] += __shfl_xor_sync(0xffffffffu, p[i], 2);
        }
        if ((lane & 3) == 0) {
            const int rb = wm * 32 + (lane >> 2);
#pragma unroll
            for (int i = 0; i < 4; i++)
                red[g * 256 + (rb + i * 8) * 2 + wn] = p[i];
        }
    };

    load_stage(0, 0);
    load_stage(1, 1);

    for (int s = 0; s < NSTG_TOT; ++s) {
        const int buf = s % 3;
        if (s < NSTG_TOT - 1) cp_wait<1>(); else cp_wait<0>();
        __syncthreads();

        // eager issue FIRST: buffer (s+2)%3 == (s-1)%3 was freed at stage s-1
        // and the sync above proves every warp left it; issuing here overlaps
        // the LSU burst with this stage's MMAs instead of the barrier tail.
        if (s + 2 < NSTG_TOT) load_stage(s + 2, (s + 2) % 3);

        const uint32_t base = sb + RED_BYTES + buf * STG_BYTES;
#pragma unroll
        for (int k16 = 0; k16 < 4; ++k16) {
            const uint32_t kb = k16 * 32;
            uint32_t ahi[2][4], alo[2][4], bh[4][4], bl[4][4];
#pragma unroll
            for (int mi = 0; mi < 2; mi++) {
                const uint32_t ao = a_base[mi] + ((kb + a_kh) ^ a_xor);
                ldsm_x4(ahi[mi], base + A_HI_OFF + ao);
                ldsm_x4(alo[mi], base + A_LO_OFF + ao);
            }
#pragma unroll
            for (int nq = 0; nq < 4; nq++) {
                const uint32_t bo = b_base[nq] + ((kb + b_kh) ^ b_xor);
                ldsm_x4(bh[nq], base + B_HI_OFF + bo);
                ldsm_x4(bl[nq], base + B_LO_OFF + bo);
            }
#pragma unroll
            for (int mi = 0; mi < 2; mi++)
#pragma unroll
                for (int nf = 0; nf < 8; nf++) {
                    const int nq = nf >> 1, hh = (nf & 1) * 2;
                    mma_bf16(acc[mi][nf], ahi[mi], bh[nq][hh], bh[nq][hh + 1]);
                    mma_bf16(acc[mi][nf], ahi[mi], bl[nq][hh], bl[nq][hh + 1]);
                    mma_bf16(acc[mi][nf], alo[mi], bh[nq][hh], bh[nq][hh + 1]);
                }
        }

        if (s == 15) {
            epilogue(0);
#pragma unroll
            for (int mi = 0; mi < 2; mi++)
#pragma unroll
                for (int nf = 0; nf < 8; nf++)
#pragma unroll
                    for (int c = 0; c < 4; c++) acc[mi][nf][c] = 0.0f;
        }
    }

    epilogue(1);
    __syncthreads();
    if (tid < NSEL) {
#pragma unroll
        for (int g = 0; g < 2; g++) {
            const float s2 = red[g * 256 + tid * 2] + red[g * 256 + tid * 2 + 1];
            g_spart[((b0 + g) * NSEL + tid) * NEBS + eb] = s2;
        }
    }
}

// ---------------------------------------------------------------------------
// Kernel 4: softmax + weighted gather-sum (float4 per thread)
// ---------------------------------------------------------------------------
__global__ void pool_kernel(const float* __restrict__ hmat, float* __restrict__ out) {
    const int b = blockIdx.x;
    const int tid = threadIdx.x;   // 0..255

    __shared__ float sc[NSEL], tmp[NSEL], alpha[NSEL];
    __shared__ int   sIdx[NSEL];

    if (tid < NSEL) {
        sIdx[tid] = g_idx[b * NSEL + tid];
        const float* p = &g_spart[(b * NSEL + tid) * NEBS];
        float s = 0.f;
#pragma unroll
        for (int i = 0; i < NEBS; i++) s += p[i];
        sc[tid] = s;
        tmp[tid] = s;
    }
    __syncthreads();
    for (int s = 64; s > 0; s >>= 1) {
        if (tid < s) tmp[tid] = fmaxf(tmp[tid], tmp[tid + s]);
        __syncthreads();
    }
    const float mx = tmp[0];
    __syncthreads();
    if (tid < NSEL) {
        const float e = expf(sc[tid] - mx);
        alpha[tid] = e;
        tmp[tid] = e;
    }
    __syncthreads();
    for (int s = 64; s > 0; s >>= 1) {
        if (tid < s) tmp[tid] += tmp[tid + s];
        __syncthreads();
    }
    const float inv = 1.0f / tmp[0];
    __syncthreads();

    float a0 = 0.f, a1 = 0.f, a2 = 0.f, a3 = 0.f;
    for (int k = 0; k < NSEL; k++) {
        const float a = alpha[k];
        const float4 v = *(reinterpret_cast<const float4*>(
            hmat + (size_t)(b * NA + sIdx[k]) * DIM) + tid);
        a0 += a * v.x; a1 += a * v.y; a2 += a * v.z; a3 += a * v.w;
    }
    float4 o;
    o.x = a0 * inv; o.y = a1 * inv; o.z = a2 * inv; o.w = a3 * inv;
    reinterpret_cast<float4*>(out + (size_t)b * DIM)[tid] = o;
}

// ---------------------------------------------------------------------------
// Inputs: h, coords, batch, is_ligand, W, b, v
// ---------------------------------------------------------------------------
extern "C" void kernel_launch(void* const* d_in, const int* in_sizes, int n_in,
                              void* d_out, int out_size) {
    const float* h      = (const float*)d_in[0];
    const float* coords = (const float*)d_in[1];
    const float* W      = (const float*)d_in[4];
    const float* bias   = (const float*)d_in[5];
    const float* v      = (const float*)d_in[6];
    float* out = (float*)d_out;

    cudaFuncSetAttribute(gemm_hmma_kernel, cudaFuncAttributeMaxDynamicSharedMemorySize, GEMM_SMEM);

    split_w_kernel<<<1024, 256>>>(W);
    select_split_kernel<<<BG, 512>>>(coords, h);
    gemm_hmma_kernel<<<dim3(NEBS, BG / 2), 256, GEMM_SMEM>>>(bias, v);
    pool_kernel<<<BG, 256>>>(h, out);
}

// round 13
// speedup vs baseline: 1.0372x; 1.0372x over previous
#include <cuda_runtime.h>
#include <cuda_bf16.h>
#include <cstdint>

// Problem geometry (fixed by setup_inputs)
#define BG    256
#define NA    512
#define NLIG  128
#define TOPK  64
#define NSEL  128
#define DIM   1024
#define NEBS  8       // e-tiles of 128

// ---------------- scratch (__device__ globals; no allocation allowed) -------
__device__ int   g_idx[BG * NSEL];
__device__ float g_spart[BG * NSEL * NEBS];
__device__ __nv_bfloat16 g_Ahi[(size_t)BG * NSEL * DIM];
__device__ __nv_bfloat16 g_Alo[(size_t)BG * NSEL * DIM];
__device__ __nv_bfloat16 g_Whi[(size_t)DIM * DIM];
__device__ __nv_bfloat16 g_Wlo[(size_t)DIM * DIM];

// ---------------- helpers ---------------------------------------------------
__device__ __forceinline__ uint32_t smem_u32(const void* p) {
    uint32_t a;
    asm("{ .reg .u64 t; cvta.to.shared.u64 t, %1; cvt.u32.u64 %0, t; }" : "=r"(a) : "l"(p));
    return a;
}
__device__ __forceinline__ void cp16(uint32_t dst, const void* src) {
    asm volatile("cp.async.cg.shared.global [%0], [%1], 16;" :: "r"(dst), "l"(src));
}
__device__ __forceinline__ void cp_commit() { asm volatile("cp.async.commit_group;" ::: "memory"); }
template <int N> __device__ __forceinline__ void cp_wait() {
    asm volatile("cp.async.wait_group %0;" :: "n"(N) : "memory");
}
__device__ __forceinline__ void ldsm_x4(uint32_t* r, uint32_t addr) {
    asm volatile("ldmatrix.sync.aligned.m8n8.x4.shared.b16 {%0,%1,%2,%3}, [%4];"
                 : "=r"(r[0]), "=r"(r[1]), "=r"(r[2]), "=r"(r[3]) : "r"(addr));
}
__device__ __forceinline__ void mma_bf16(float* d, const uint32_t* a, uint32_t b0, uint32_t b1) {
    asm volatile("mma.sync.aligned.m16n8k16.row.col.f32.bf16.bf16.f32 "
                 "{%0,%1,%2,%3}, {%4,%5,%6,%7}, {%8,%9}, {%0,%1,%2,%3};"
                 : "+f"(d[0]), "+f"(d[1]), "+f"(d[2]), "+f"(d[3])
                 : "r"(a[0]), "r"(a[1]), "r"(a[2]), "r"(a[3]), "r"(b0), "r"(b1));
}
// tanh via exact identity 1 - 2/(e^{2x}+1) with MUFU ex2/rcp (~1e-6 error)
__device__ __forceinline__ float tanh_fast(float x) {
    float e, r;
    asm("ex2.approx.f32 %0, %1;" : "=f"(e) : "f"(x * 2.885390081777927f));
    asm("rcp.approx.f32 %0, %1;" : "=f"(r) : "f"(e + 1.0f));
    return fmaf(-2.0f, r, 1.0f);
}

// ---------------------------------------------------------------------------
// Kernel 1: FUSED selection + gather/split of A.
// One block of 512 threads per graph. Phase 1: centroids + distances +
// deterministic rank top-K into smem (and g_idx for pool). Phase 2: all 512
// threads gather the 128 selected h rows and write (A_hi, A_lo) bf16.
// ---------------------------------------------------------------------------
__global__ __launch_bounds__(512)
void select_split_kernel(const float* __restrict__ coords, const float* __restrict__ h) {
    const int b = blockIdx.x;
    const int t = threadIdx.x;  // 0..511

    __shared__ float px[16], py[16], pz[16];
    __shared__ float cent[6];
    __shared__ float d2[NA];
    __shared__ int   sIdx[NSEL];

    const float* cp = coords + (size_t)(b * NA + t) * 3;
    float x = cp[0], y = cp[1], z = cp[2];

    float wx = x, wy = y, wz = z;
#pragma unroll
    for (int o = 16; o > 0; o >>= 1) {
        wx += __shfl_down_sync(0xffffffffu, wx, o);
        wy += __shfl_down_sync(0xffffffffu, wy, o);
        wz += __shfl_down_sync(0xffffffffu, wz, o);
    }
    const int wid = t >> 5, lane = t & 31;
    if (lane == 0) { px[wid] = wx; py[wid] = wy; pz[wid] = wz; }
    __syncthreads();

    if (t == 0) {
        float tx = 0, ty = 0, tz = 0, lx = 0, ly = 0, lz = 0;
        for (int i = 0; i < 16; i++) { tx += px[i]; ty += py[i]; tz += pz[i]; }
        for (int i = 0; i < 4; i++)  { lx += px[i]; ly += py[i]; lz += pz[i]; }
        const float invl = 1.0f / NLIG, invp = 1.0f / (NA - NLIG);
        cent[3] = lx * invl;        cent[4] = ly * invl;        cent[5] = lz * invl;
        cent[0] = (tx - lx) * invp; cent[1] = (ty - ly) * invp; cent[2] = (tz - lz) * invp;
    }
    __syncthreads();

    float cx, cy, cz;
    if (t < NLIG) { cx = cent[0]; cy = cent[1]; cz = cent[2]; }
    else          { cx = cent[3]; cy = cent[4]; cz = cent[5]; }
    const float dx = x - cx, dy = y - cy, dz = z - cz;
    d2[t] = dx * dx + dy * dy + dz * dz;
    __syncthreads();

    const float mine = d2[t];
    int rank = 0;
    if (t < NLIG) {
        for (int j = 0; j < NLIG; j++) {
            const float o = d2[j];
            rank += (o < mine) || (o == mine && j < t);
        }
        if (rank < TOPK) { sIdx[TOPK + rank] = t; g_idx[b * NSEL + TOPK + rank] = t; }
    } else {
        for (int j = NLIG; j < NA; j++) {
            const float o = d2[j];
            rank += (o < mine) || (o == mine && j < t);
        }
        if (rank < TOPK) { sIdx[rank] = t; g_idx[b * NSEL + rank] = t; }
    }
    __syncthreads();

    // Phase 2: gather + split. 128 rows x 256 float4 = 32768 float4, 512 threads.
#pragma unroll
    for (int j = 0; j < 64; j++) {
        const int i = t + j * 512;
        const int r = i >> 8, c4 = i & 255;
        const float4 v = *reinterpret_cast<const float4*>(
            h + ((size_t)(b * NA + sIdx[r])) * DIM + c4 * 4);
        __nv_bfloat162 h01 = __floats2bfloat162_rn(v.x, v.y);
        __nv_bfloat162 h23 = __floats2bfloat162_rn(v.z, v.w);
        __nv_bfloat162 l01 = __floats2bfloat162_rn(v.x - __bfloat162float(h01.x),
                                                   v.y - __bfloat162float(h01.y));
        __nv_bfloat162 l23 = __floats2bfloat162_rn(v.z - __bfloat162float(h23.x),
                                                   v.w - __bfloat162float(h23.y));
        const size_t o = ((size_t)(b * NSEL + r)) * DIM + c4 * 4;
        *reinterpret_cast<__nv_bfloat162*>(g_Ahi + o)     = h01;
        *reinterpret_cast<__nv_bfloat162*>(g_Ahi + o + 2) = h23;
        *reinterpret_cast<__nv_bfloat162*>(g_Alo + o)     = l01;
        *reinterpret_cast<__nv_bfloat162*>(g_Alo + o + 2) = l23;
    }
}

// ---------------------------------------------------------------------------
// Kernel 2: split W -> (W_hi, W_lo) bf16
// ---------------------------------------------------------------------------
__global__ void split_w_kernel(const float* __restrict__ W) {
    const size_t i = (size_t)blockIdx.x * 256 + threadIdx.x;
    const float4 v = reinterpret_cast<const float4*>(W)[i];
    __nv_bfloat162 h01 = __floats2bfloat162_rn(v.x, v.y);
    __nv_bfloat162 h23 = __floats2bfloat162_rn(v.z, v.w);
    __nv_bfloat162 l01 = __floats2bfloat162_rn(v.x - __bfloat162float(h01.x),
                                               v.y - __bfloat162float(h01.y));
    __nv_bfloat162 l23 = __floats2bfloat162_rn(v.z - __bfloat162float(h23.x),
                                               v.w - __bfloat162float(h23.y));
    const size_t o = i * 4;
    *reinterpret_cast<__nv_bfloat162*>(g_Whi + o)     = h01;
    *reinterpret_cast<__nv_bfloat162*>(g_Whi + o + 2) = h23;
    *reinterpret_cast<__nv_bfloat162*>(g_Wlo + o)     = l01;
    *reinterpret_cast<__nv_bfloat162*>(g_Wlo + o + 2) = l23;
}

// ---------------------------------------------------------------------------
// Kernel 3: HMMA bf16 split-GEMM + fused tanh/v epilogue.
// Grid (8, 128): x = 128-wide e-tile, y = pair of graphs (2 per CTA).
// 8 warps (4 M x 2 N), warp tile 32x64, 3 HMMA passes (hh, hl, lh).
// Kc=64, 3-stage ring, ONE sync per stage; loads for stage s+2 issued
// AFTER the compute block (R8 order — issuing before compute delays the
// stage's ldsm stream at the LSU and measurably regresses).
// 32 stages = 2 graphs x 16 k-chunks; graph-0 epilogue runs inline.
// smem: red 2KB | 3 stages x 64KB = 198656 B.
// ---------------------------------------------------------------------------
#define NSTG_TOT  32
#define STG_BYTES 65536
#define A_HI_OFF  0
#define A_LO_OFF  16384
#define B_HI_OFF  32768
#define B_LO_OFF  49152
#define RED_BYTES 2048
#define GEMM_SMEM (RED_BYTES + 3 * STG_BYTES)

__global__ __launch_bounds__(256, 1)
void gemm_hmma_kernel(const float* __restrict__ bias, const float* __restrict__ vvec) {
    extern __shared__ __align__(1024) char smem[];
    const uint32_t sb = smem_u32(smem);
    const int tid = threadIdx.x, wid = tid >> 5, lane = tid & 31;
    const int eb = blockIdx.x, b0 = blockIdx.y * 2;
    const int wm = wid >> 1, wn = wid & 1;     // 4 M x 2 N, warp tile 32x64

    const char* Ah[2] = { (const char*)g_Ahi + (size_t)b0 * NSEL * 2048,
                          (const char*)g_Ahi + (size_t)(b0 + 1) * NSEL * 2048 };
    const char* Al[2] = { (const char*)g_Alo + (size_t)b0 * NSEL * 2048,
                          (const char*)g_Alo + (size_t)(b0 + 1) * NSEL * 2048 };
    const char* Bh = (const char*)g_Whi + (size_t)eb * 128 * 2048;
    const char* Bl = (const char*)g_Wlo + (size_t)eb * 128 * 2048;

    float* red = reinterpret_cast<float*>(smem);   // [2][128][2]

    // stage loader: 4 tiles of 128 rows x 128 bytes, XOR-swizzled
    auto load_stage = [&](int S, int buf) {
        const int g = S >> 4, kc = S & 15;
        const uint32_t base = sb + RED_BYTES + buf * STG_BYTES;
        const int k0b = kc * 128;
#pragma unroll
        for (int j = 0; j < 4; j++) {
            const int i = tid + j * 256;
            const int r = i >> 3, sg = i & 7;
            const uint32_t off = r * 128 + ((sg * 16) ^ ((r & 7) << 4));
            const size_t go = (size_t)r * 2048 + k0b + sg * 16;
            cp16(base + A_HI_OFF + off, Ah[g] + go);
            cp16(base + A_LO_OFF + off, Al[g] + go);
            cp16(base + B_HI_OFF + off, Bh + go);
            cp16(base + B_LO_OFF + off, Bl + go);
        }
        cp_commit();
    };

    float acc[2][8][4];
#pragma unroll
    for (int mi = 0; mi < 2; mi++)
#pragma unroll
        for (int nf = 0; nf < 8; nf++)
#pragma unroll
            for (int c = 0; c < 4; c++) acc[mi][nf][c] = 0.0f;

    // per-lane ldmatrix address components
    const int arow = lane & 15;
    const uint32_t a_kh = (lane >> 4) * 16;
    const uint32_t a_xor = (uint32_t)((arow & 7) << 4);
    uint32_t a_base[2];
#pragma unroll
    for (int mi = 0; mi < 2; mi++)
        a_base[mi] = (uint32_t)((wm * 32 + mi * 16 + arow) * 128);

    const int brl = (lane & 7) + ((lane >> 4) << 3);
    const uint32_t b_kh = ((lane >> 3) & 1) * 16;
    const uint32_t b_xor = (uint32_t)((lane & 7) << 4);
    uint32_t b_base[4];
#pragma unroll
    for (int nq = 0; nq < 4; nq++)
        b_base[nq] = (uint32_t)((wn * 64 + nq * 16 + brl) * 128);

    // epilogue: tanh + v-dot on this thread's accs, write per-graph red slab
    auto epilogue = [&](int g) {
        float p[4] = {0.f, 0.f, 0.f, 0.f};
#pragma unroll
        for (int mi = 0; mi < 2; mi++)
#pragma unroll
            for (int nf = 0; nf < 8; nf++) {
                const int e0 = eb * 128 + wn * 64 + nf * 8 + (lane & 3) * 2;
                const float bb0 = __ldg(bias + e0), bb1 = __ldg(bias + e0 + 1);
                const float vv0 = __ldg(vvec + e0), vv1 = __ldg(vvec + e0 + 1);
                p[mi * 2 + 0] += tanh_fast(acc[mi][nf][0] + bb0) * vv0
                               + tanh_fast(acc[mi][nf][1] + bb1) * vv1;
                p[mi * 2 + 1] += tanh_fast(acc[mi][nf][2] + bb0) * vv0
                               + tanh_fast(acc[mi][nf][3] + bb1) * vv1;
            }
#pragma unroll
        for (int i = 0; i < 4; i++) {
            p[i] += __shfl_xor_sync(0xffffffffu, p[i], 1);
            p[i] += __shfl_xor_sync(0xffffffffu, p[i], 2);
        }
        if ((lane & 3) == 0) {
            const int rb = wm * 32 + (lane >> 2);
#pragma unroll
            for (int i = 0; i < 4; i++)
                red[g * 256 + (rb + i * 8) * 2 + wn] = p[i];
        }
    };

    load_stage(0, 0);
    load_stage(1, 1);

    for (int s = 0; s < NSTG_TOT; ++s) {
        const int buf = s % 3;
        if (s < NSTG_TOT - 1) cp_wait<1>(); else cp_wait<0>();
        __syncthreads();

        const uint32_t base = sb + RED_BYTES + buf * STG_BYTES;
#pragma unroll
        for (int k16 = 0; k16 < 4; ++k16) {
            const uint32_t kb = k16 * 32;
            uint32_t ahi[2][4], alo[2][4], bh[4][4], bl[4][4];
#pragma unroll
            for (int mi = 0; mi < 2; mi++) {
                const uint32_t ao = a_base[mi] + ((kb + a_kh) ^ a_xor);
                ldsm_x4(ahi[mi], base + A_HI_OFF + ao);
                ldsm_x4(alo[mi], base + A_LO_OFF + ao);
            }
#pragma unroll
            for (int nq = 0; nq < 4; nq++) {
                const uint32_t bo = b_base[nq] + ((kb + b_kh) ^ b_xor);
                ldsm_x4(bh[nq], base + B_HI_OFF + bo);
                ldsm_x4(bl[nq], base + B_LO_OFF + bo);
            }
#pragma unroll
            for (int mi = 0; mi < 2; mi++)
#pragma unroll
                for (int nf = 0; nf < 8; nf++) {
                    const int nq = nf >> 1, hh = (nf & 1) * 2;
                    mma_bf16(acc[mi][nf], ahi[mi], bh[nq][hh], bh[nq][hh + 1]);
                    mma_bf16(acc[mi][nf], ahi[mi], bl[nq][hh], bl[nq][hh + 1]);
                    mma_bf16(acc[mi][nf], alo[mi], bh[nq][hh], bh[nq][hh + 1]);
                }
        }

        // eager issue AFTER compute (R8 order): buffer (s+2)%3 == (s-1)%3 was
        // freed at stage s-1 and the top-of-s sync proves every warp left it.
        if (s + 2 < NSTG_TOT) load_stage(s + 2, (s + 2) % 3);

        if (s == 15) {
            epilogue(0);
#pragma unroll
            for (int mi = 0; mi < 2; mi++)
#pragma unroll
                for (int nf = 0; nf < 8; nf++)
#pragma unroll
                    for (int c = 0; c < 4; c++) acc[mi][nf][c] = 0.0f;
        }
    }

    epilogue(1);
    __syncthreads();
    if (tid < NSEL) {
#pragma unroll
        for (int g = 0; g < 2; g++) {
            const float s2 = red[g * 256 + tid * 2] + red[g * 256 + tid * 2 + 1];
            g_spart[((b0 + g) * NSEL + tid) * NEBS + eb] = s2;
        }
    }
}

// ---------------------------------------------------------------------------
// Kernel 4: softmax + weighted gather-sum.
// Grid (BG, 2), 128 threads: each block covers 128 float4 columns (half of D);
// softmax recomputed per block (cheap). k-loop unrolled x4 for MLP.
// ---------------------------------------------------------------------------
__global__ __launch_bounds__(128)
void pool_kernel(const float* __restrict__ hmat, float* __restrict__ out) {
    const int b = blockIdx.x;
    const int half = blockIdx.y;
    const int tid = threadIdx.x;   // 0..127

    __shared__ float tmp[NSEL], alpha[NSEL];
    __shared__ int   sIdx[NSEL];

    sIdx[tid] = g_idx[b * NSEL + tid];
    const float* pp = &g_spart[(b * NSEL + tid) * NEBS];
    float sc = 0.f;
#pragma unroll
    for (int i = 0; i < NEBS; i++) sc += pp[i];
    tmp[tid] = sc;
    __syncthreads();
    for (int s = 64; s > 0; s >>= 1) {
        if (tid < s) tmp[tid] = fmaxf(tmp[tid], tmp[tid + s]);
        __syncthreads();
    }
    const float mx = tmp[0];
    __syncthreads();
    const float e = expf(sc - mx);
    alpha[tid] = e;
    tmp[tid] = e;
    __syncthreads();
    for (int s = 64; s > 0; s >>= 1) {
        if (tid < s) tmp[tid] += tmp[tid + s];
        __syncthreads();
    }
    const float inv = 1.0f / tmp[0];
    __syncthreads();

    const int c4 = half * 128 + tid;   // this thread's float4 column
    float a0 = 0.f, a1 = 0.f, a2 = 0.f, a3 = 0.f;
#pragma unroll 4
    for (int k = 0; k < NSEL; k++) {
        const float a = alpha[k];
        const float4 v = *(reinterpret_cast<const float4*>(
            hmat + (size_t)(b * NA + sIdx[k]) * DIM) + c4);
        a0 += a * v.x; a1 += a * v.y; a2 += a * v.z; a3 += a * v.w;
    }
    float4 o;
    o.x = a0 * inv; o.y = a1 * inv; o.z = a2 * inv; o.w = a3 * inv;
    reinterpret_cast<float4*>(out + (size_t)b * DIM)[c4] = o;
}

// ---------------------------------------------------------------------------
// Inputs: h, coords, batch, is_ligand, W, b, v
// ---------------------------------------------------------------------------
extern "C" void kernel_launch(void* const* d_in, const int* in_sizes, int n_in,
                              void* d_out, int out_size) {
    const float* h      = (const float*)d_in[0];
    const float* coords = (const float*)d_in[1];
    const float* W      = (const float*)d_in[4];
    const float* bias   = (const float*)d_in[5];
    const float* v      = (const float*)d_in[6];
    float* out = (float*)d_out;

    cudaFuncSetAttribute(gemm_hmma_kernel, cudaFuncAttributeMaxDynamicSharedMemorySize, GEMM_SMEM);

    split_w_kernel<<<1024, 256>>>(W);
    select_split_kernel<<<BG, 512>>>(coords, h);
    gemm_hmma_kernel<<<dim3(NEBS, BG / 2), 256, GEMM_SMEM>>>(bias, v);
    pool_kernel<<<dim3(BG, 2), 128>>>(h, out);
}

// round 14
// speedup vs baseline: 1.0464x; 1.0088x over previous
#include <cuda_runtime.h>
#include <cuda_bf16.h>
#include <cstdint>

// Problem geometry (fixed by setup_inputs)
#define BG    256
#define NA    512
#define NLIG  128
#define TOPK  64
#define NSEL  128
#define DIM   1024
#define NEBS  8       // e-tiles of 128

// ---------------- scratch (__device__ globals; no allocation allowed) -------
__device__ int   g_idx[BG * NSEL];
__device__ float g_spart[BG * NSEL * NEBS];
__device__ __nv_bfloat16 g_Ahi[(size_t)BG * NSEL * DIM];
__device__ __nv_bfloat16 g_Alo[(size_t)BG * NSEL * DIM];
__device__ __nv_bfloat16 g_Whi[(size_t)DIM * DIM];
__device__ __nv_bfloat16 g_Wlo[(size_t)DIM * DIM];

// ---------------- helpers ---------------------------------------------------
__device__ __forceinline__ uint32_t smem_u32(const void* p) {
    uint32_t a;
    asm("{ .reg .u64 t; cvta.to.shared.u64 t, %1; cvt.u32.u64 %0, t; }" : "=r"(a) : "l"(p));
    return a;
}
__device__ __forceinline__ void cp16(uint32_t dst, const void* src) {
    asm volatile("cp.async.cg.shared.global [%0], [%1], 16;" :: "r"(dst), "l"(src));
}
__device__ __forceinline__ void cp_commit() { asm volatile("cp.async.commit_group;" ::: "memory"); }
template <int N> __device__ __forceinline__ void cp_wait() {
    asm volatile("cp.async.wait_group %0;" :: "n"(N) : "memory");
}
__device__ __forceinline__ void ldsm_x4(uint32_t* r, uint32_t addr) {
    asm volatile("ldmatrix.sync.aligned.m8n8.x4.shared.b16 {%0,%1,%2,%3}, [%4];"
                 : "=r"(r[0]), "=r"(r[1]), "=r"(r[2]), "=r"(r[3]) : "r"(addr));
}
__device__ __forceinline__ void mma_bf16(float* d, const uint32_t* a, uint32_t b0, uint32_t b1) {
    asm volatile("mma.sync.aligned.m16n8k16.row.col.f32.bf16.bf16.f32 "
                 "{%0,%1,%2,%3}, {%4,%5,%6,%7}, {%8,%9}, {%0,%1,%2,%3};"
                 : "+f"(d[0]), "+f"(d[1]), "+f"(d[2]), "+f"(d[3])
                 : "r"(a[0]), "r"(a[1]), "r"(a[2]), "r"(a[3]), "r"(b0), "r"(b1));
}
// tanh via exact identity 1 - 2/(e^{2x}+1) with MUFU ex2/rcp (~1e-6 error)
__device__ __forceinline__ float tanh_fast(float x) {
    float e, r;
    asm("ex2.approx.f32 %0, %1;" : "=f"(e) : "f"(x * 2.885390081777927f));
    asm("rcp.approx.f32 %0, %1;" : "=f"(r) : "f"(e + 1.0f));
    return fmaf(-2.0f, r, 1.0f);
}

// ---------------------------------------------------------------------------
// Kernel 1: FUSED selection + gather/split of A.
// ---------------------------------------------------------------------------
__global__ __launch_bounds__(512)
void select_split_kernel(const float* __restrict__ coords, const float* __restrict__ h) {
    const int b = blockIdx.x;
    const int t = threadIdx.x;  // 0..511

    __shared__ float px[16], py[16], pz[16];
    __shared__ float cent[6];
    __shared__ float d2[NA];
    __shared__ int   sIdx[NSEL];

    const float* cp = coords + (size_t)(b * NA + t) * 3;
    float x = cp[0], y = cp[1], z = cp[2];

    float wx = x, wy = y, wz = z;
#pragma unroll
    for (int o = 16; o > 0; o >>= 1) {
        wx += __shfl_down_sync(0xffffffffu, wx, o);
        wy += __shfl_down_sync(0xffffffffu, wy, o);
        wz += __shfl_down_sync(0xffffffffu, wz, o);
    }
    const int wid = t >> 5, lane = t & 31;
    if (lane == 0) { px[wid] = wx; py[wid] = wy; pz[wid] = wz; }
    __syncthreads();

    if (t == 0) {
        float tx = 0, ty = 0, tz = 0, lx = 0, ly = 0, lz = 0;
        for (int i = 0; i < 16; i++) { tx += px[i]; ty += py[i]; tz += pz[i]; }
        for (int i = 0; i < 4; i++)  { lx += px[i]; ly += py[i]; lz += pz[i]; }
        const float invl = 1.0f / NLIG, invp = 1.0f / (NA - NLIG);
        cent[3] = lx * invl;        cent[4] = ly * invl;        cent[5] = lz * invl;
        cent[0] = (tx - lx) * invp; cent[1] = (ty - ly) * invp; cent[2] = (tz - lz) * invp;
    }
    __syncthreads();

    float cx, cy, cz;
    if (t < NLIG) { cx = cent[0]; cy = cent[1]; cz = cent[2]; }
    else          { cx = cent[3]; cy = cent[4]; cz = cent[5]; }
    const float dx = x - cx, dy = y - cy, dz = z - cz;
    d2[t] = dx * dx + dy * dy + dz * dz;
    __syncthreads();

    const float mine = d2[t];
    int rank = 0;
    if (t < NLIG) {
        for (int j = 0; j < NLIG; j++) {
            const float o = d2[j];
            rank += (o < mine) || (o == mine && j < t);
        }
        if (rank < TOPK) { sIdx[TOPK + rank] = t; g_idx[b * NSEL + TOPK + rank] = t; }
    } else {
        for (int j = NLIG; j < NA; j++) {
            const float o = d2[j];
            rank += (o < mine) || (o == mine && j < t);
        }
        if (rank < TOPK) { sIdx[rank] = t; g_idx[b * NSEL + rank] = t; }
    }
    __syncthreads();

    // Phase 2: gather + split. 128 rows x 256 float4 = 32768 float4, 512 threads.
#pragma unroll
    for (int j = 0; j < 64; j++) {
        const int i = t + j * 512;
        const int r = i >> 8, c4 = i & 255;
        const float4 v = *reinterpret_cast<const float4*>(
            h + ((size_t)(b * NA + sIdx[r])) * DIM + c4 * 4);
        __nv_bfloat162 h01 = __floats2bfloat162_rn(v.x, v.y);
        __nv_bfloat162 h23 = __floats2bfloat162_rn(v.z, v.w);
        __nv_bfloat162 l01 = __floats2bfloat162_rn(v.x - __bfloat162float(h01.x),
                                                   v.y - __bfloat162float(h01.y));
        __nv_bfloat162 l23 = __floats2bfloat162_rn(v.z - __bfloat162float(h23.x),
                                                   v.w - __bfloat162float(h23.y));
        const size_t o = ((size_t)(b * NSEL + r)) * DIM + c4 * 4;
        *reinterpret_cast<__nv_bfloat162*>(g_Ahi + o)     = h01;
        *reinterpret_cast<__nv_bfloat162*>(g_Ahi + o + 2) = h23;
        *reinterpret_cast<__nv_bfloat162*>(g_Alo + o)     = l01;
        *reinterpret_cast<__nv_bfloat162*>(g_Alo + o + 2) = l23;
    }
}

// ---------------------------------------------------------------------------
// Kernel 2: split W -> (W_hi, W_lo) bf16
// ---------------------------------------------------------------------------
__global__ void split_w_kernel(const float* __restrict__ W) {
    const size_t i = (size_t)blockIdx.x * 256 + threadIdx.x;
    const float4 v = reinterpret_cast<const float4*>(W)[i];
    __nv_bfloat162 h01 = __floats2bfloat162_rn(v.x, v.y);
    __nv_bfloat162 h23 = __floats2bfloat162_rn(v.z, v.w);
    __nv_bfloat162 l01 = __floats2bfloat162_rn(v.x - __bfloat162float(h01.x),
                                               v.y - __bfloat162float(h01.y));
    __nv_bfloat162 l23 = __floats2bfloat162_rn(v.z - __bfloat162float(h23.x),
                                               v.w - __bfloat162float(h23.y));
    const size_t o = i * 4;
    *reinterpret_cast<__nv_bfloat162*>(g_Whi + o)     = h01;
    *reinterpret_cast<__nv_bfloat162*>(g_Whi + o + 2) = h23;
    *reinterpret_cast<__nv_bfloat162*>(g_Wlo + o)     = l01;
    *reinterpret_cast<__nv_bfloat162*>(g_Wlo + o + 2) = l23;
}

// ---------------------------------------------------------------------------
// Kernel 3: HMMA bf16 split-GEMM + fused tanh/v epilogue.
// Grid (8, 128). 8 warps (4 M x 2 N), warp tile 32x64, 3 HMMA passes.
// Kc=64, 3-stage ring, one sync/stage, eager load AFTER compute (R8 order).
// NEW: register fragment double-buffering at half-k16 granularity — the
// ldsm stream for the next half/k16 is issued while the current 24 MMAs run,
// breaking the per-warp ldsm->MMA serial dependency.
// smem: red 2KB | 3 stages x 64KB = 198656 B.
// ---------------------------------------------------------------------------
#define NSTG_TOT  32
#define STG_BYTES 65536
#define A_HI_OFF  0
#define A_LO_OFF  16384
#define B_HI_OFF  32768
#define B_LO_OFF  49152
#define RED_BYTES 2048
#define GEMM_SMEM (RED_BYTES + 3 * STG_BYTES)

__global__ __launch_bounds__(256, 1)
void gemm_hmma_kernel(const float* __restrict__ bias, const float* __restrict__ vvec) {
    extern __shared__ __align__(1024) char smem[];
    const uint32_t sb = smem_u32(smem);
    const int tid = threadIdx.x, wid = tid >> 5, lane = tid & 31;
    const int eb = blockIdx.x, b0 = blockIdx.y * 2;
    const int wm = wid >> 1, wn = wid & 1;     // 4 M x 2 N, warp tile 32x64

    const char* Ah[2] = { (const char*)g_Ahi + (size_t)b0 * NSEL * 2048,
                          (const char*)g_Ahi + (size_t)(b0 + 1) * NSEL * 2048 };
    const char* Al[2] = { (const char*)g_Alo + (size_t)b0 * NSEL * 2048,
                          (const char*)g_Alo + (size_t)(b0 + 1) * NSEL * 2048 };
    const char* Bh = (const char*)g_Whi + (size_t)eb * 128 * 2048;
    const char* Bl = (const char*)g_Wlo + (size_t)eb * 128 * 2048;

    float* red = reinterpret_cast<float*>(smem);   // [2][128][2]

    // stage loader: 4 tiles of 128 rows x 128 bytes, XOR-swizzled
    auto load_stage = [&](int S, int buf) {
        const int g = S >> 4, kc = S & 15;
        const uint32_t base = sb + RED_BYTES + buf * STG_BYTES;
        const int k0b = kc * 128;
#pragma unroll
        for (int j = 0; j < 4; j++) {
            const int i = tid + j * 256;
            const int r = i >> 3, sg = i & 7;
            const uint32_t off = r * 128 + ((sg * 16) ^ ((r & 7) << 4));
            const size_t go = (size_t)r * 2048 + k0b + sg * 16;
            cp16(base + A_HI_OFF + off, Ah[g] + go);
            cp16(base + A_LO_OFF + off, Al[g] + go);
            cp16(base + B_HI_OFF + off, Bh + go);
            cp16(base + B_LO_OFF + off, Bl + go);
        }
        cp_commit();
    };

    float acc[2][8][4];
#pragma unroll
    for (int mi = 0; mi < 2; mi++)
#pragma unroll
        for (int nf = 0; nf < 8; nf++)
#pragma unroll
            for (int c = 0; c < 4; c++) acc[mi][nf][c] = 0.0f;

    // per-lane ldmatrix address components
    const int arow = lane & 15;
    const uint32_t a_kh = (lane >> 4) * 16;
    const uint32_t a_xor = (uint32_t)((arow & 7) << 4);
    uint32_t a_base[2];
#pragma unroll
    for (int mi = 0; mi < 2; mi++)
        a_base[mi] = (uint32_t)((wm * 32 + mi * 16 + arow) * 128);

    const int brl = (lane & 7) + ((lane >> 4) << 3);
    const uint32_t b_kh = ((lane >> 3) & 1) * 16;
    const uint32_t b_xor = (uint32_t)((lane & 7) << 4);
    uint32_t b_base[4];
#pragma unroll
    for (int nq = 0; nq < 4; nq++)
        b_base[nq] = (uint32_t)((wn * 64 + nq * 16 + brl) * 128);

    // register fragment double buffers
    uint32_t aF[2][16];   // [buf][ ahi(mi0:0-3, mi1:4-7) | alo(8-15) ]
    uint32_t bF[2][16];   // [buf][ bh(q0:0-3, q1:4-7)    | bl(8-15) ]

    auto ldA = [&](int fb, uint32_t base, uint32_t kb) {
#pragma unroll
        for (int mi = 0; mi < 2; mi++) {
            const uint32_t ao = a_base[mi] + ((kb + a_kh) ^ a_xor);
            ldsm_x4(&aF[fb][mi * 4],     base + A_HI_OFF + ao);
            ldsm_x4(&aF[fb][8 + mi * 4], base + A_LO_OFF + ao);
        }
    };
    auto ldB = [&](int fb, uint32_t base, uint32_t kb, int half) {
#pragma unroll
        for (int q = 0; q < 2; q++) {
            const uint32_t bo = b_base[half * 2 + q] + ((kb + b_kh) ^ b_xor);
            ldsm_x4(&bF[fb][q * 4],     base + B_HI_OFF + bo);
            ldsm_x4(&bF[fb][8 + q * 4], base + B_LO_OFF + bo);
        }
    };
    auto domma = [&](int ab, int bb, int half) {
#pragma unroll
        for (int mi = 0; mi < 2; mi++)
#pragma unroll
            for (int f = 0; f < 4; f++) {
                const int nf = half * 4 + f;
                const int q = f >> 1, hh = (f & 1) * 2;
                mma_bf16(acc[mi][nf], &aF[ab][mi * 4],     bF[bb][q * 4 + hh],     bF[bb][q * 4 + hh + 1]);
                mma_bf16(acc[mi][nf], &aF[ab][mi * 4],     bF[bb][8 + q * 4 + hh], bF[bb][8 + q * 4 + hh + 1]);
                mma_bf16(acc[mi][nf], &aF[ab][8 + mi * 4], bF[bb][q * 4 + hh],     bF[bb][q * 4 + hh + 1]);
            }
    };

    // epilogue: tanh + v-dot on this thread's accs, write per-graph red slab
    auto epilogue = [&](int g) {
        float p[4] = {0.f, 0.f, 0.f, 0.f};
#pragma unroll
        for (int mi = 0; mi < 2; mi++)
#pragma unroll
            for (int nf = 0; nf < 8; nf++) {
                const int e0 = eb * 128 + wn * 64 + nf * 8 + (lane & 3) * 2;
                const float bb0 = __ldg(bias + e0), bb1 = __ldg(bias + e0 + 1);
                const float vv0 = __ldg(vvec + e0), vv1 = __ldg(vvec + e0 + 1);
                p[mi * 2 + 0] += tanh_fast(acc[mi][nf][0] + bb0) * vv0
                               + tanh_fast(acc[mi][nf][1] + bb1) * vv1;
                p[mi * 2 + 1] += tanh_fast(acc[mi][nf][2] + bb0) * vv0
                               + tanh_fast(acc[mi][nf][3] + bb1) * vv1;
            }
#pragma unroll
        for (int i = 0; i < 4; i++) {
            p[i] += __shfl_xor_sync(0xffffffffu, p[i], 1);
            p[i] += __shfl_xor_sync(0xffffffffu, p[i], 2);
        }
        if ((lane & 3) == 0) {
            const int rb = wm * 32 + (lane >> 2);
#pragma unroll
            for (int i = 0; i < 4; i++)
                red[g * 256 + (rb + i * 8) * 2 + wn] = p[i];
        }
    };

    load_stage(0, 0);
    load_stage(1, 1);

    for (int s = 0; s < NSTG_TOT; ++s) {
        const int buf = s % 3;
        if (s < NSTG_TOT - 1) cp_wait<1>(); else cp_wait<0>();
        __syncthreads();

        const uint32_t base = sb + RED_BYTES + buf * STG_BYTES;

        // fragment pipeline: prologue loads for k16=0 half=0
        ldA(0, base, 0);
        ldB(0, base, 0, 0);
        int ab = 0, bb = 0;
#pragma unroll
        for (int k16 = 0; k16 < 4; ++k16) {
            const uint32_t kb = k16 * 32;
            // half 0: prefetch B half1, then MMA on (ab, bb)
            ldB(bb ^ 1, base, kb, 1);
            domma(ab, bb, 0);
            bb ^= 1;
            // half 1: prefetch next k16's A and B half0, then MMA
            if (k16 < 3) {
                ldA(ab ^ 1, base, kb + 32);
                ldB(bb ^ 1, base, kb + 32, 0);
            }
            domma(ab, bb, 1);
            bb ^= 1;
            ab ^= 1;
        }

        // eager issue AFTER compute (R8 order): buffer (s+2)%3 == (s-1)%3 was
        // freed at stage s-1 and the top-of-s sync proves every warp left it.
        if (s + 2 < NSTG_TOT) load_stage(s + 2, (s + 2) % 3);

        if (s == 15) {
            epilogue(0);
#pragma unroll
            for (int mi = 0; mi < 2; mi++)
#pragma unroll
                for (int nf = 0; nf < 8; nf++)
#pragma unroll
                    for (int c = 0; c < 4; c++) acc[mi][nf][c] = 0.0f;
        }
    }

    epilogue(1);
    __syncthreads();
    if (tid < NSEL) {
#pragma unroll
        for (int g = 0; g < 2; g++) {
            const float s2 = red[g * 256 + tid * 2] + red[g * 256 + tid * 2 + 1];
            g_spart[((b0 + g) * NSEL + tid) * NEBS + eb] = s2;
        }
    }
}

// ---------------------------------------------------------------------------
// Kernel 4: softmax + weighted gather-sum.
// Grid (BG), 256 threads, one float4 column per thread; gather loop batched
// 8 rows at a time (8 independent loads in flight -> latency hidden).
// ---------------------------------------------------------------------------
__global__ __launch_bounds__(256)
void pool_kernel(const float* __restrict__ hmat, float* __restrict__ out) {
    const int b = blockIdx.x;
    const int tid = threadIdx.x;   // 0..255

    __shared__ float tmp[NSEL], alpha[NSEL];
    __shared__ int   sIdx[NSEL];

    if (tid < NSEL) {
        sIdx[tid] = g_idx[b * NSEL + tid];
        const float* pp = &g_spart[(b * NSEL + tid) * NEBS];
        float sc = 0.f;
#pragma unroll
        for (int i = 0; i < NEBS; i++) sc += pp[i];
        alpha[tid] = sc;       // temp: raw score
        tmp[tid] = sc;
    }
    __syncthreads();
    for (int s = 64; s > 0; s >>= 1) {
        if (tid < s) tmp[tid] = fmaxf(tmp[tid], tmp[tid + s]);
        __syncthreads();
    }
    const float mx = tmp[0];
    __syncthreads();
    if (tid < NSEL) {
        const float e = expf(alpha[tid] - mx);
        alpha[tid] = e;
        tmp[tid] = e;
    }
    __syncthreads();
    for (int s = 64; s > 0; s >>= 1) {
        if (tid < s) tmp[tid] += tmp[tid + s];
        __syncthreads();
    }
    const float inv = 1.0f / tmp[0];
    __syncthreads();

    float a0 = 0.f, a1 = 0.f, a2 = 0.f, a3 = 0.f;
    for (int k0 = 0; k0 < NSEL; k0 += 8) {
        float4 v[8];
#pragma unroll
        for (int j = 0; j < 8; j++)
            v[j] = *(reinterpret_cast<const float4*>(
                hmat + (size_t)(b * NA + sIdx[k0 + j]) * DIM) + tid);
#pragma unroll
        for (int j = 0; j < 8; j++) {
            const float a = alpha[k0 + j];
            a0 += a * v[j].x; a1 += a * v[j].y; a2 += a * v[j].z; a3 += a * v[j].w;
        }
    }
    float4 o;
    o.x = a0 * inv; o.y = a1 * inv; o.z = a2 * inv; o.w = a3 * inv;
    reinterpret_cast<float4*>(out + (size_t)b * DIM)[tid] = o;
}

// ---------------------------------------------------------------------------
// Inputs: h, coords, batch, is_ligand, W, b, v
// ---------------------------------------------------------------------------
extern "C" void kernel_launch(void* const* d_in, const int* in_sizes, int n_in,
                              void* d_out, int out_size) {
    const float* h      = (const float*)d_in[0];
    const float* coords = (const float*)d_in[1];
    const float* W      = (const float*)d_in[4];
    const float* bias   = (const float*)d_in[5];
    const float* v      = (const float*)d_in[6];
    float* out = (float*)d_out;

    cudaFuncSetAttribute(gemm_hmma_kernel, cudaFuncAttributeMaxDynamicSharedMemorySize, GEMM_SMEM);

    split_w_kernel<<<1024, 256>>>(W);
    select_split_kernel<<<BG, 512>>>(coords, h);
    gemm_hmma_kernel<<<dim3(NEBS, BG / 2), 256, GEMM_SMEM>>>(bias, v);
    pool_kernel<<<BG, 256>>>(h, out);
}

// round 15
// speedup vs baseline: 1.0492x; 1.0027x over previous
#include <cuda_runtime.h>
#include <cuda_bf16.h>
#include <cstdint>

// Problem geometry (fixed by setup_inputs)
#define BG    256
#define NA    512
#define NLIG  128
#define TOPK  64
#define NSEL  128
#define DIM   1024
#define NEBS  8       // e-tiles of 128

// ---------------- scratch (__device__ globals; no allocation allowed) -------
__device__ int   g_idx[BG * NSEL];
__device__ float g_spart[BG * NSEL * NEBS];
__device__ __nv_bfloat16 g_Ahi[(size_t)BG * NSEL * DIM];
__device__ __nv_bfloat16 g_Alo[(size_t)BG * NSEL * DIM];
__device__ __nv_bfloat16 g_Whi[(size_t)DIM * DIM];
__device__ __nv_bfloat16 g_Wlo[(size_t)DIM * DIM];

// ---------------- helpers ---------------------------------------------------
__device__ __forceinline__ uint32_t smem_u32(const void* p) {
    uint32_t a;
    asm("{ .reg .u64 t; cvta.to.shared.u64 t, %1; cvt.u32.u64 %0, t; }" : "=r"(a) : "l"(p));
    return a;
}
__device__ __forceinline__ void cp16(uint32_t dst, const void* src) {
    asm volatile("cp.async.cg.shared.global [%0], [%1], 16;" :: "r"(dst), "l"(src));
}
__device__ __forceinline__ void cp_commit() { asm volatile("cp.async.commit_group;" ::: "memory"); }
template <int N> __device__ __forceinline__ void cp_wait() {
    asm volatile("cp.async.wait_group %0;" :: "n"(N) : "memory");
}
__device__ __forceinline__ void ldsm_x4(uint32_t* r, uint32_t addr) {
    asm volatile("ldmatrix.sync.aligned.m8n8.x4.shared.b16 {%0,%1,%2,%3}, [%4];"
                 : "=r"(r[0]), "=r"(r[1]), "=r"(r[2]), "=r"(r[3]) : "r"(addr));
}
__device__ __forceinline__ void mma_bf16(float* d, const uint32_t* a, uint32_t b0, uint32_t b1) {
    asm volatile("mma.sync.aligned.m16n8k16.row.col.f32.bf16.bf16.f32 "
                 "{%0,%1,%2,%3}, {%4,%5,%6,%7}, {%8,%9}, {%0,%1,%2,%3};"
                 : "+f"(d[0]), "+f"(d[1]), "+f"(d[2]), "+f"(d[3])
                 : "r"(a[0]), "r"(a[1]), "r"(a[2]), "r"(a[3]), "r"(b0), "r"(b1));
}
// tanh via exact identity 1 - 2/(e^{2x}+1) with MUFU ex2/rcp (~1e-6 error)
__device__ __forceinline__ float tanh_fast(float x) {
    float e, r;
    asm("ex2.approx.f32 %0, %1;" : "=f"(e) : "f"(x * 2.885390081777927f));
    asm("rcp.approx.f32 %0, %1;" : "=f"(r) : "f"(e + 1.0f));
    return fmaf(-2.0f, r, 1.0f);
}
// split a float4 into packed (hi, lo) bf16x2-pair uint2s
__device__ __forceinline__ void split4(const float4 v, uint2& uh, uint2& ul) {
    __nv_bfloat162 h01 = __floats2bfloat162_rn(v.x, v.y);
    __nv_bfloat162 h23 = __floats2bfloat162_rn(v.z, v.w);
    __nv_bfloat162 l01 = __floats2bfloat162_rn(v.x - __bfloat162float(h01.x),
                                               v.y - __bfloat162float(h01.y));
    __nv_bfloat162 l23 = __floats2bfloat162_rn(v.z - __bfloat162float(h23.x),
                                               v.w - __bfloat162float(h23.y));
    uh.x = *reinterpret_cast<uint32_t*>(&h01);
    uh.y = *reinterpret_cast<uint32_t*>(&h23);
    ul.x = *reinterpret_cast<uint32_t*>(&l01);
    ul.y = *reinterpret_cast<uint32_t*>(&l23);
}

// ---------------------------------------------------------------------------
// Kernel 1: FUSED selection + gather/split of A + this block's slice of W.
// One block of 512 threads per graph (256 blocks total).
// ---------------------------------------------------------------------------
__global__ __launch_bounds__(512)
void select_split_kernel(const float* __restrict__ coords, const float* __restrict__ h,
                         const float* __restrict__ W) {
    const int b = blockIdx.x;
    const int t = threadIdx.x;  // 0..511

    __shared__ float px[16], py[16], pz[16];
    __shared__ float cent[6];
    __shared__ float d2[NA];
    __shared__ int   sIdx[NSEL];

    const float* cp = coords + (size_t)(b * NA + t) * 3;
    float x = cp[0], y = cp[1], z = cp[2];

    float wx = x, wy = y, wz = z;
#pragma unroll
    for (int o = 16; o > 0; o >>= 1) {
        wx += __shfl_down_sync(0xffffffffu, wx, o);
        wy += __shfl_down_sync(0xffffffffu, wy, o);
        wz += __shfl_down_sync(0xffffffffu, wz, o);
    }
    const int wid = t >> 5, lane = t & 31;
    if (lane == 0) { px[wid] = wx; py[wid] = wy; pz[wid] = wz; }
    __syncthreads();

    if (t == 0) {
        float tx = 0, ty = 0, tz = 0, lx = 0, ly = 0, lz = 0;
        for (int i = 0; i < 16; i++) { tx += px[i]; ty += py[i]; tz += pz[i]; }
        for (int i = 0; i < 4; i++)  { lx += px[i]; ly += py[i]; lz += pz[i]; }
        const float invl = 1.0f / NLIG, invp = 1.0f / (NA - NLIG);
        cent[3] = lx * invl;        cent[4] = ly * invl;        cent[5] = lz * invl;
        cent[0] = (tx - lx) * invp; cent[1] = (ty - ly) * invp; cent[2] = (tz - lz) * invp;
    }
    __syncthreads();

    float cx, cy, cz;
    if (t < NLIG) { cx = cent[0]; cy = cent[1]; cz = cent[2]; }
    else          { cx = cent[3]; cy = cent[4]; cz = cent[5]; }
    const float dx = x - cx, dy = y - cy, dz = z - cz;
    d2[t] = dx * dx + dy * dy + dz * dz;
    __syncthreads();

    const float mine = d2[t];
    int rank = 0;
    if (t < NLIG) {
        for (int j = 0; j < NLIG; j++) {
            const float o = d2[j];
            rank += (o < mine) || (o == mine && j < t);
        }
        if (rank < TOPK) { sIdx[TOPK + rank] = t; g_idx[b * NSEL + TOPK + rank] = t; }
    } else {
        for (int j = NLIG; j < NA; j++) {
            const float o = d2[j];
            rank += (o < mine) || (o == mine && j < t);
        }
        if (rank < TOPK) { sIdx[rank] = t; g_idx[b * NSEL + rank] = t; }
    }
    __syncthreads();

    // Phase 2: gather + split A. 128 rows x 256 float4, 512 threads.
#pragma unroll
    for (int j = 0; j < 64; j++) {
        const int i = t + j * 512;
        const int r = i >> 8, c4 = i & 255;
        const float4 v = *reinterpret_cast<const float4*>(
            h + ((size_t)(b * NA + sIdx[r])) * DIM + c4 * 4);
        uint2 uh, ul;
        split4(v, uh, ul);
        const size_t o = ((size_t)(b * NSEL + r)) * DIM + c4 * 4;
        *reinterpret_cast<uint2*>(g_Ahi + o) = uh;
        *reinterpret_cast<uint2*>(g_Alo + o) = ul;
    }

    // Phase 3 (independent): this block's 1/256 slice of W -> (W_hi, W_lo).
#pragma unroll
    for (int j = 0; j < 2; j++) {
        const size_t i = (size_t)b * 1024 + t + j * 512;   // float4 index
        const float4 v = reinterpret_cast<const float4*>(W)[i];
        uint2 uh, ul;
        split4(v, uh, ul);
        const size_t o = i * 4;
        *reinterpret_cast<uint2*>(g_Whi + o) = uh;
        *reinterpret_cast<uint2*>(g_Wlo + o) = ul;
    }
}

// ---------------------------------------------------------------------------
// Kernel 2: HMMA bf16 split-GEMM + fused tanh/v epilogue. (R14, unchanged)
// Grid (8, 128). 8 warps (4 M x 2 N), warp tile 32x64, 3 HMMA passes.
// Kc=64, 3-stage ring, one sync/stage, eager load AFTER compute,
// register fragment double-buffering at half-k16 granularity.
// smem: red 2KB | 3 stages x 64KB = 198656 B.
// ---------------------------------------------------------------------------
#define NSTG_TOT  32
#define STG_BYTES 65536
#define A_HI_OFF  0
#define A_LO_OFF  16384
#define B_HI_OFF  32768
#define B_LO_OFF  49152
#define RED_BYTES 2048
#define GEMM_SMEM (RED_BYTES + 3 * STG_BYTES)

__global__ __launch_bounds__(256, 1)
void gemm_hmma_kernel(const float* __restrict__ bias, const float* __restrict__ vvec) {
    extern __shared__ __align__(1024) char smem[];
    const uint32_t sb = smem_u32(smem);
    const int tid = threadIdx.x, wid = tid >> 5, lane = tid & 31;
    const int eb = blockIdx.x, b0 = blockIdx.y * 2;
    const int wm = wid >> 1, wn = wid & 1;     // 4 M x 2 N, warp tile 32x64

    const char* Ah[2] = { (const char*)g_Ahi + (size_t)b0 * NSEL * 2048,
                          (const char*)g_Ahi + (size_t)(b0 + 1) * NSEL * 2048 };
    const char* Al[2] = { (const char*)g_Alo + (size_t)b0 * NSEL * 2048,
                          (const char*)g_Alo + (size_t)(b0 + 1) * NSEL * 2048 };
    const char* Bh = (const char*)g_Whi + (size_t)eb * 128 * 2048;
    const char* Bl = (const char*)g_Wlo + (size_t)eb * 128 * 2048;

    float* red = reinterpret_cast<float*>(smem);   // [2][128][2]

    // stage loader: 4 tiles of 128 rows x 128 bytes, XOR-swizzled
    auto load_stage = [&](int S, int buf) {
        const int g = S >> 4, kc = S & 15;
        const uint32_t base = sb + RED_BYTES + buf * STG_BYTES;
        const int k0b = kc * 128;
#pragma unroll
        for (int j = 0; j < 4; j++) {
            const int i = tid + j * 256;
            const int r = i >> 3, sg = i & 7;
            const uint32_t off = r * 128 + ((sg * 16) ^ ((r & 7) << 4));
            const size_t go = (size_t)r * 2048 + k0b + sg * 16;
            cp16(base + A_HI_OFF + off, Ah[g] + go);
            cp16(base + A_LO_OFF + off, Al[g] + go);
            cp16(base + B_HI_OFF + off, Bh + go);
            cp16(base + B_LO_OFF + off, Bl + go);
        }
        cp_commit();
    };

    float acc[2][8][4];
#pragma unroll
    for (int mi = 0; mi < 2; mi++)
#pragma unroll
        for (int nf = 0; nf < 8; nf++)
#pragma unroll
            for (int c = 0; c < 4; c++) acc[mi][nf][c] = 0.0f;

    // per-lane ldmatrix address components
    const int arow = lane & 15;
    const uint32_t a_kh = (lane >> 4) * 16;
    const uint32_t a_xor = (uint32_t)((arow & 7) << 4);
    uint32_t a_base[2];
#pragma unroll
    for (int mi = 0; mi < 2; mi++)
        a_base[mi] = (uint32_t)((wm * 32 + mi * 16 + arow) * 128);

    const int brl = (lane & 7) + ((lane >> 4) << 3);
    const uint32_t b_kh = ((lane >> 3) & 1) * 16;
    const uint32_t b_xor = (uint32_t)((lane & 7) << 4);
    uint32_t b_base[4];
#pragma unroll
    for (int nq = 0; nq < 4; nq++)
        b_base[nq] = (uint32_t)((wn * 64 + nq * 16 + brl) * 128);

    // register fragment double buffers
    uint32_t aF[2][16];   // [buf][ ahi(mi0:0-3, mi1:4-7) | alo(8-15) ]
    uint32_t bF[2][16];   // [buf][ bh(q0:0-3, q1:4-7)    | bl(8-15) ]

    auto ldA = [&](int fb, uint32_t base, uint32_t kb) {
#pragma unroll
        for (int mi = 0; mi < 2; mi++) {
            const uint32_t ao = a_base[mi] + ((kb + a_kh) ^ a_xor);
            ldsm_x4(&aF[fb][mi * 4],     base + A_HI_OFF + ao);
            ldsm_x4(&aF[fb][8 + mi * 4], base + A_LO_OFF + ao);
        }
    };
    auto ldB = [&](int fb, uint32_t base, uint32_t kb, int half) {
#pragma unroll
        for (int q = 0; q < 2; q++) {
            const uint32_t bo = b_base[half * 2 + q] + ((kb + b_kh) ^ b_xor);
            ldsm_x4(&bF[fb][q * 4],     base + B_HI_OFF + bo);
            ldsm_x4(&bF[fb][8 + q * 4], base + B_LO_OFF + bo);
        }
    };
    auto domma = [&](int ab, int bb, int half) {
#pragma unroll
        for (int mi = 0; mi < 2; mi++)
#pragma unroll
            for (int f = 0; f < 4; f++) {
                const int nf = half * 4 + f;
                const int q = f >> 1, hh = (f & 1) * 2;
                mma_bf16(acc[mi][nf], &aF[ab][mi * 4],     bF[bb][q * 4 + hh],     bF[bb][q * 4 + hh + 1]);
                mma_bf16(acc[mi][nf], &aF[ab][mi * 4],     bF[bb][8 + q * 4 + hh], bF[bb][8 + q * 4 + hh + 1]);
                mma_bf16(acc[mi][nf], &aF[ab][8 + mi * 4], bF[bb][q * 4 + hh],     bF[bb][q * 4 + hh + 1]);
            }
    };

    // epilogue: tanh + v-dot on this thread's accs, write per-graph red slab
    auto epilogue = [&](int g) {
        float p[4] = {0.f, 0.f, 0.f, 0.f};
#pragma unroll
        for (int mi = 0; mi < 2; mi++)
#pragma unroll
            for (int nf = 0; nf < 8; nf++) {
                const int e0 = eb * 128 + wn * 64 + nf * 8 + (lane & 3) * 2;
                const float bb0 = __ldg(bias + e0), bb1 = __ldg(bias + e0 + 1);
                const float vv0 = __ldg(vvec + e0), vv1 = __ldg(vvec + e0 + 1);
                p[mi * 2 + 0] += tanh_fast(acc[mi][nf][0] + bb0) * vv0
                               + tanh_fast(acc[mi][nf][1] + bb1) * vv1;
                p[mi * 2 + 1] += tanh_fast(acc[mi][nf][2] + bb0) * vv0
                               + tanh_fast(acc[mi][nf][3] + bb1) * vv1;
            }
#pragma unroll
        for (int i = 0; i < 4; i++) {
            p[i] += __shfl_xor_sync(0xffffffffu, p[i], 1);
            p[i] += __shfl_xor_sync(0xffffffffu, p[i], 2);
        }
        if ((lane & 3) == 0) {
            const int rb = wm * 32 + (lane >> 2);
#pragma unroll
            for (int i = 0; i < 4; i++)
                red[g * 256 + (rb + i * 8) * 2 + wn] = p[i];
        }
    };

    load_stage(0, 0);
    load_stage(1, 1);

    for (int s = 0; s < NSTG_TOT; ++s) {
        const int buf = s % 3;
        if (s < NSTG_TOT - 1) cp_wait<1>(); else cp_wait<0>();
        __syncthreads();

        const uint32_t base = sb + RED_BYTES + buf * STG_BYTES;

        // fragment pipeline: prologue loads for k16=0 half=0
        ldA(0, base, 0);
        ldB(0, base, 0, 0);
        int ab = 0, bb = 0;
#pragma unroll
        for (int k16 = 0; k16 < 4; ++k16) {
            const uint32_t kb = k16 * 32;
            ldB(bb ^ 1, base, kb, 1);
            domma(ab, bb, 0);
            bb ^= 1;
            if (k16 < 3) {
                ldA(ab ^ 1, base, kb + 32);
                ldB(bb ^ 1, base, kb + 32, 0);
            }
            domma(ab, bb, 1);
            bb ^= 1;
            ab ^= 1;
        }

        // eager issue AFTER compute (R8 order)
        if (s + 2 < NSTG_TOT) load_stage(s + 2, (s + 2) % 3);

        if (s == 15) {
            epilogue(0);
#pragma unroll
            for (int mi = 0; mi < 2; mi++)
#pragma unroll
                for (int nf = 0; nf < 8; nf++)
#pragma unroll
                    for (int c = 0; c < 4; c++) acc[mi][nf][c] = 0.0f;
        }
    }

    epilogue(1);
    __syncthreads();
    if (tid < NSEL) {
#pragma unroll
        for (int g = 0; g < 2; g++) {
            const float s2 = red[g * 256 + tid * 2] + red[g * 256 + tid * 2 + 1];
            g_spart[((b0 + g) * NSEL + tid) * NEBS + eb] = s2;
        }
    }
}

// ---------------------------------------------------------------------------
// Kernel 3: softmax + weighted gather-sum.
// Grid (BG), 256 threads, one float4 column per thread; gather loop batched
// 16 rows at a time (16 independent loads in flight -> latency hidden).
// ---------------------------------------------------------------------------
__global__ __launch_bounds__(256)
void pool_kernel(const float* __restrict__ hmat, float* __restrict__ out) {
    const int b = blockIdx.x;
    const int tid = threadIdx.x;   // 0..255

    __shared__ float tmp[NSEL], alpha[NSEL];
    __shared__ int   sIdx[NSEL];

    if (tid < NSEL) {
        sIdx[tid] = g_idx[b * NSEL + tid];
        const float* pp = &g_spart[(b * NSEL + tid) * NEBS];
        float sc = 0.f;
#pragma unroll
        for (int i = 0; i < NEBS; i++) sc += pp[i];
        alpha[tid] = sc;       // temp: raw score
        tmp[tid] = sc;
    }
    __syncthreads();
    for (int s = 64; s > 0; s >>= 1) {
        if (tid < s) tmp[tid] = fmaxf(tmp[tid], tmp[tid + s]);
        __syncthreads();
    }
    const float mx = tmp[0];
    __syncthreads();
    if (tid < NSEL) {
        const float e = expf(alpha[tid] - mx);
        alpha[tid] = e;
        tmp[tid] = e;
    }
    __syncthreads();
    for (int s = 64; s > 0; s >>= 1) {
        if (tid < s) tmp[tid] += tmp[tid + s];
        __syncthreads();
    }
    const float inv = 1.0f / tmp[0];
    __syncthreads();

    float a0 = 0.f, a1 = 0.f, a2 = 0.f, a3 = 0.f;
    for (int k0 = 0; k0 < NSEL; k0 += 16) {
        float4 v[16];
#pragma unroll
        for (int j = 0; j < 16; j++)
            v[j] = *(reinterpret_cast<const float4*>(
                hmat + (size_t)(b * NA + sIdx[k0 + j]) * DIM) + tid);
#pragma unroll
        for (int j = 0; j < 16; j++) {
            const float a = alpha[k0 + j];
            a0 += a * v[j].x; a1 += a * v[j].y; a2 += a * v[j].z; a3 += a * v[j].w;
        }
    }
    float4 o;
    o.x = a0 * inv; o.y = a1 * inv; o.z = a2 * inv; o.w = a3 * inv;
    reinterpret_cast<float4*>(out + (size_t)b * DIM)[tid] = o;
}

// ---------------------------------------------------------------------------
// Inputs: h, coords, batch, is_ligand, W, b, v
// ---------------------------------------------------------------------------
extern "C" void kernel_launch(void* const* d_in, const int* in_sizes, int n_in,
                              void* d_out, int out_size) {
    const float* h      = (const float*)d_in[0];
    const float* coords = (const float*)d_in[1];
    const float* W      = (const float*)d_in[4];
    const float* bias   = (const float*)d_in[5];
    const float* v      = (const float*)d_in[6];
    float* out = (float*)d_out;

    cudaFuncSetAttribute(gemm_hmma_kernel, cudaFuncAttributeMaxDynamicSharedMemorySize, GEMM_SMEM);

    select_split_kernel<<<BG, 512>>>(coords, h, W);
    gemm_hmma_kernel<<<dim3(NEBS, BG / 2), 256, GEMM_SMEM>>>(bias, v);
    pool_kernel<<<BG, 256>>>(h, out);
}